// round 16
// baseline (speedup 1.0000x reference)
#include <cuda_runtime.h>

// MeanConv: out = (1/7) * sum_{k in {3,5,7,9,11,13,15}} box_mean_k(x, replicate pad) * mask
//
// R14 = R7 structure at half block size for 2.5x occupancy.
//  TW=128, NTH=128 (4 warps), CHUNK=4, SH=64, RING=32 (18.4 KB smem).
//  __launch_bounds__(128,10) -> target 10 CTAs/SM = 40 warps/SM.
//  Producer (per-warp row ownership, register prefetch, warp shfl scan) and
//  consumer (runtime-indexed ring, 7 vertical running sums) identical to R7.

#define H_DIM 4096
#define W_DIM 4096
#define TW    128
#define NTH   128
#define SH    64
#define HALO  7
#define NROWVALS (TW + 2*HALO)     // 142
#define TWP      144               // padded smem row stride (fits prefix 0..142)
#define RING     32
#define CHUNK    4                 // rows per chunk == warps per block
#define NCHUNK   (SH / CHUNK)      // 16

__device__ __forceinline__ int clampi(int v, int lo, int hi) { return min(max(v, lo), hi); }

__global__ __launch_bounds__(NTH, 10)
void meanconv_kernel(const float* __restrict__ x,
                     const float* __restrict__ mask,
                     float* __restrict__ out)
{
    __shared__ float ring[RING][TWP];

    const int t    = threadIdx.x;
    const int lane = t & 31;
    const int wrp  = t >> 5;                   // 0..3
    const int c0   = blockIdx.x * TW;
    const int r0   = blockIdx.y * SH;
    const int j    = t + HALO;                 // center position in a prefix row

    // ---- warp w loads global row (base_row + w), clamped, into registers ----
    auto load_rows = [&](int base_row, float (&pf)[5]) {
        const int grc = clampi(base_row + wrp, 0, H_DIM - 1);
        const float* __restrict__ rowp = x + (size_t)grc * W_DIM;
        #pragma unroll
        for (int i = 0; i < 4; i++) {
            const int gc = clampi(c0 - HALO + lane + 32 * i, 0, W_DIM - 1);
            pf[i] = rowp[gc];
        }
        if (lane < NROWVALS - 128) {           // lane < 14
            const int gc = clampi(c0 - HALO + lane + 128, 0, W_DIM - 1);
            pf[4] = rowp[gc];
        }
    };

    // ---- warp w: STS raw row, warp-sync, in-place prefix scan (P[0..142]) ----
    auto commit_rows = [&](int base_row, const float (&pf)[5]) {
        float* __restrict__ row = ring[(base_row + wrp) & (RING - 1)];
        #pragma unroll
        for (int i = 0; i < 4; i++) row[lane + 32 * i] = pf[i];
        if (lane < NROWVALS - 128) row[lane + 128] = pf[4];
        __syncwarp();

        const int base = lane * 5;             // lanes 0..28 cover 0..141
        float ps[5];
        float tot = 0.0f;
        if (base < NROWVALS) {
            float s = 0.0f;
            #pragma unroll
            for (int i = 0; i < 5; i++) {
                if (base + i < NROWVALS) s += row[base + i];
                ps[i] = s;
            }
            tot = s;
        }
        float inc = tot;
        #pragma unroll
        for (int d = 1; d < 32; d <<= 1) {
            float n = __shfl_up_sync(0xffffffffu, inc, d);
            if (lane >= d) inc += n;
        }
        const float excl = inc - tot;
        __syncwarp();                          // raw reads done before overwrite
        if (lane == 0) row[0] = 0.0f;
        if (base < NROWVALS) {
            #pragma unroll
            for (int i = 0; i < 5; i++)
                if (base + i < NROWVALS) row[base + i + 1] = excl + ps[i];
        }
    };

    float pf[5];

    // ---- preload rows r0-8 .. r0+7 (4 chunks); prefetch rows r0+8..r0+11 ----
    load_rows(r0 - 8, pf);  commit_rows(r0 - 8, pf);
    load_rows(r0 - 4, pf);  commit_rows(r0 - 4, pf);
    load_rows(r0,     pf);  commit_rows(r0,     pf);
    load_rows(r0 + 4, pf);  commit_rows(r0 + 4, pf);
    load_rows(r0 + 8, pf);                     // chunk 0 raw rows -> registers
    __syncthreads();

    // ---- init vertical running sums: acc[ki] covers rows [r0-hk, r0+hk] ----
    float acc[7];
    #pragma unroll
    for (int ki = 0; ki < 7; ki++) {
        const int hk = ki + 1;                 // k = 2*hk+1
        float a = 0.0f;
        #pragma unroll
        for (int d = -7; d <= 7; d++) {
            if (d < -hk || d > hk) continue;
            const float* __restrict__ rp = &ring[(r0 + d) & (RING - 1)][j];
            a += rp[hk + 1] - rp[-hk];
        }
        acc[ki] = a;
    }

    // ---- main sweep: 1 barrier per 4-row chunk; prefetch overlaps consume ----
    for (int c = 0; c < NCHUNK; c++) {
        const int prow = r0 + 8 + c * CHUNK;   // rows produced this chunk
        commit_rows(prow, pf);                 // STS + warp-local scan
        if (c + 1 < NCHUNK)
            load_rows(prow + CHUNK, pf);       // prefetch next chunk (hidden)
        __syncthreads();                       // scanned rows visible to all

        const int crow = r0 + c * CHUNK;
        size_t idx = (size_t)crow * W_DIM + (size_t)(c0 + t);

        #pragma unroll
        for (int rr = 0; rr < CHUNK; rr++) {
            const int r = crow + rr;

            float s = acc[0] * (1.0f / (7.0f *   9.0f));
            s = fmaf(acc[1], 1.0f / (7.0f *  25.0f), s);
            s = fmaf(acc[2], 1.0f / (7.0f *  49.0f), s);
            s = fmaf(acc[3], 1.0f / (7.0f *  81.0f), s);
            s = fmaf(acc[4], 1.0f / (7.0f * 121.0f), s);
            s = fmaf(acc[5], 1.0f / (7.0f * 169.0f), s);
            s = fmaf(acc[6], 1.0f / (7.0f * 225.0f), s);
            out[idx] = s * mask[idx];

            #pragma unroll
            for (int ki = 0; ki < 7; ki++) {
                const int hk = ki + 1;
                const float* __restrict__ ra = &ring[(r + 1 + hk) & (RING - 1)][j];
                const float* __restrict__ rs = &ring[(r - hk)     & (RING - 1)][j];
                acc[ki] += (ra[hk + 1] - ra[-hk]) - (rs[hk + 1] - rs[-hk]);
            }
            idx += W_DIM;
        }
        // hazard bound: fastest warp's next commit writes slot-rows
        // (crow+12..crow+15) mod 32; slowest warp still reads rows
        // (crow-7..crow+11) mod 32 — disjoint. Barrier bounds skew to 1 chunk.
    }
}

extern "C" void kernel_launch(void* const* d_in, const int* in_sizes, int n_in,
                              void* d_out, int out_size)
{
    const float* x    = (const float*)d_in[0];
    const float* mask = (const float*)d_in[1];
    float* out        = (float*)d_out;

    dim3 grid(W_DIM / TW, H_DIM / SH);
    dim3 block(NTH);
    meanconv_kernel<<<grid, block>>>(x, mask, out);
}